// round 3
// baseline (speedup 1.0000x reference)
#include <cuda_runtime.h>

#define D      256
#define Kc     1024
#define NROWS  32768
#define Z_ELEMS 8388608

#define TM 64
#define TN 64
#define TK 16
#define BS_STRIDE 68   // 64 + 4 pad: 272B rows keep 16B alignment, no bank conflicts

typedef unsigned long long u64;

__device__ float g_cnorm[Kc];
__device__ float g_znorm[NROWS];
__device__ int   g_idx[NROWS];
__device__ float g_loss;

// packed f32x2 FMA: two independent IEEE fp32 RN FMAs per instruction.
// Bit-identical per lane to scalar fmaf -> accumulation chains unchanged.
__device__ __forceinline__ void fma2(u64& d, u64 a, u64 b) {
    asm("fma.rn.f32x2 %0, %1, %2, %0;" : "+l"(d) : "l"(a), "l"(b));
}
__device__ __forceinline__ float lo32(u64 v) { return __uint_as_float((unsigned)v); }
__device__ __forceinline__ float hi32(u64 v) { return __uint_as_float((unsigned)(v >> 32)); }

// ---------------------------------------------------------------------------
// k0: per-code squared norms, sequential ascending fp32, UNFUSED mul+add.
// ---------------------------------------------------------------------------
__global__ void prep_kernel(const float* __restrict__ cb) {
    int k = blockIdx.x * blockDim.x + threadIdx.x;
    if (k == 0 && blockIdx.x == 0) g_loss = 0.0f;
    if (k < Kc) {
        const float* row = cb + (size_t)k * D;
        float s = 0.0f;
        for (int i = 0; i < D; ++i) {
            float v = row[i];
            s = __fadd_rn(s, __fmul_rn(v, v));
        }
        g_cnorm[k] = s;
    }
}

// ---------------------------------------------------------------------------
// k0b: per-row squared norms, sequential ascending d, UNFUSED fp32 (bit-exact).
// ---------------------------------------------------------------------------
__global__ void znorm_kernel(const float* __restrict__ z) {
    int n = blockIdx.x * blockDim.x + threadIdx.x;
    int b  = n >> 10;
    int hw = n & 1023;
    const float* base = z + (size_t)b * (D * 1024) + hw;
    float s = 0.0f;
    #pragma unroll 8
    for (int d = 0; d < D; ++d) {
        float v = base[(size_t)d * 1024];
        s = __fadd_rn(s, __fmul_rn(v, v));
    }
    g_znorm[n] = s;
}

// ---------------------------------------------------------------------------
// k1: fused distance-GEMM + argmin. FFMA2 mainloop:
//   8 packed accumulators hold the 4x4 micro-tile; per-chain order = ascending
//   d sequential FMA (bit-identical to reference-matching scalar version).
//   B tile kept twice: normal and pair-swapped, so cross-term operands load
//   pre-packed (no MOV packs in the loop).
// ---------------------------------------------------------------------------
__global__ void __launch_bounds__(256, 2)
argmin_kernel(const float* __restrict__ z, const float* __restrict__ cb,
              float* __restrict__ out_idx_f) {
    extern __shared__ float sm[];
    float* Zs     = sm;                          // [256][64]
    float* Bs     = Zs + D * TM;                 // [16][BS_STRIDE]
    float* Bsw    = Bs + TK * BS_STRIDE;         // [16][BS_STRIDE] pair-swapped
    float* red_s  = Bsw + TK * BS_STRIDE;        // [16][64]
    int*   red_i  = (int*)(red_s + 16 * TM);     // [16][64]
    float* best_s = (float*)(red_i + 16 * TM);   // [64]
    int*   best_i = (int*)(best_s + TM);         // [64]
    float* zn_s   = (float*)(best_i + TM);       // [64]

    const int t  = threadIdx.x;
    const int tx = t & 15;    // rows = tx*4 + i
    const int ty = t >> 4;    // codes = ty*4 + j
    const int n0 = blockIdx.x * TM;
    const int b  = n0 >> 10;
    const int hw = n0 & 1023;
    const float* zb = z + (size_t)b * (D * 1024) + hw;

    for (int i = t; i < D * TM; i += 256) {
        int d = i >> 6, r = i & 63;
        Zs[i] = zb[(size_t)d * 1024 + r];
    }
    if (t < TM) {
        best_s[t] = 3.4e38f;
        best_i[t] = 0;
        zn_s[t]   = g_znorm[n0 + t];
    }
    __syncthreads();

    for (int ct = 0; ct < Kc / TN; ++ct) {
        // accD[ip][jp] = (acc[2ip][2jp]  , acc[2ip+1][2jp+1])
        // accX[ip][jp] = (acc[2ip][2jp+1], acc[2ip+1][2jp]  )
        u64 accD[2][2] = {{0ull, 0ull}, {0ull, 0ull}};
        u64 accX[2][2] = {{0ull, 0ull}, {0ull, 0ull}};
        const float* cbt = cb + (size_t)(ct * TN) * D;

        for (int d0 = 0; d0 < D; d0 += TK) {
            {
                int d  = t & 15;
                int c0 = t >> 4;
                #pragma unroll
                for (int cc = 0; cc < 4; ++cc) {
                    int c = c0 + cc * 16;
                    float v = cbt[(size_t)c * D + d0 + d];
                    Bs [d * BS_STRIDE + c]       = v;
                    Bsw[d * BS_STRIDE + (c ^ 1)] = v;   // pair-swapped copy
                }
            }
            __syncthreads();
            #pragma unroll
            for (int k = 0; k < TK; ++k) {
                ulonglong2 ap = *(const ulonglong2*)&Zs [(d0 + k) * TM + (tx << 2)];
                ulonglong2 bp = *(const ulonglong2*)&Bs [k * BS_STRIDE + (ty << 2)];
                ulonglong2 bw = *(const ulonglong2*)&Bsw[k * BS_STRIDE + (ty << 2)];
                fma2(accD[0][0], ap.x, bp.x);
                fma2(accD[0][1], ap.x, bp.y);
                fma2(accD[1][0], ap.y, bp.x);
                fma2(accD[1][1], ap.y, bp.y);
                fma2(accX[0][0], ap.x, bw.x);
                fma2(accX[0][1], ap.x, bw.y);
                fma2(accX[1][0], ap.y, bw.x);
                fma2(accX[1][1], ap.y, bw.y);
            }
            __syncthreads();
        }

        // Unpack to scalar 4x4 micro-tile
        float acc[4][4];
        #pragma unroll
        for (int ip = 0; ip < 2; ++ip)
            #pragma unroll
            for (int jp = 0; jp < 2; ++jp) {
                acc[2*ip  ][2*jp  ] = lo32(accD[ip][jp]);
                acc[2*ip+1][2*jp+1] = hi32(accD[ip][jp]);
                acc[2*ip  ][2*jp+1] = lo32(accX[ip][jp]);
                acc[2*ip+1][2*jp  ] = hi32(accX[ip][jp]);
            }

        float cn[4];
        #pragma unroll
        for (int j = 0; j < 4; ++j) cn[j] = g_cnorm[ct * TN + (ty << 2) + j];

        #pragma unroll
        for (int i = 0; i < 4; ++i) {
            int row = (tx << 2) + i;
            float zn = zn_s[row];
            float bs;
            int   bj = 0;
            {
                float t1 = __fadd_rn(zn, cn[0]);
                bs = __fadd_rn(t1, __fmul_rn(-2.0f, acc[i][0]));
            }
            #pragma unroll
            for (int j = 1; j < 4; ++j) {
                float t1 = __fadd_rn(zn, cn[j]);
                float s  = __fadd_rn(t1, __fmul_rn(-2.0f, acc[i][j]));
                if (s < bs) { bs = s; bj = j; }
            }
            red_s[ty * TM + row] = bs;
            red_i[ty * TM + row] = ct * TN + (ty << 2) + bj;
        }
        __syncthreads();
        if (t < TM) {
            float bs = best_s[t]; int bi = best_i[t];
            #pragma unroll
            for (int g = 0; g < 16; ++g) {
                float s = red_s[g * TM + t];
                if (s < bs) { bs = s; bi = red_i[g * TM + t]; }
            }
            best_s[t] = bs; best_i[t] = bi;
        }
        __syncthreads();
    }

    if (t < TM) {
        int n = n0 + t;
        g_idx[n]     = best_i[t];
        out_idx_f[n] = (float)best_i[t];
    }
}

// ---------------------------------------------------------------------------
// k2: tiled gather + STE + loss. All GMEM traffic coalesced:
//   - 32 codebook rows staged to smem (contiguous d reads)
//   - z reads / out writes contiguous along hw
// ---------------------------------------------------------------------------
__global__ void __launch_bounds__(256)
gather_kernel(const float* __restrict__ z, const float* __restrict__ cb,
              float* __restrict__ out) {
    __shared__ float q_s[32][257];
    __shared__ int   ci_s[32];
    __shared__ float rs[256];

    const int t  = threadIdx.x;
    const int n0 = blockIdx.x * 32;
    const int b  = n0 >> 10;
    const int hw0 = n0 & 1023;

    if (t < 32) ci_s[t] = g_idx[n0 + t];
    __syncthreads();

    for (int i = t; i < 32 * 256; i += 256) {
        int j = i >> 8, d = i & 255;
        q_s[j][d] = cb[(size_t)ci_s[j] * D + d];
    }
    __syncthreads();

    const float* zb = z   + (size_t)b * (D * 1024) + hw0;
    float*       ob = out + (size_t)b * (D * 1024) + hw0;
    float ls = 0.0f;
    #pragma unroll 4
    for (int i = t; i < 32 * 256; i += 256) {
        int d = i >> 5, j = i & 31;
        float zv   = zb[(size_t)d * 1024 + j];
        float q    = q_s[j][d];
        float diff = __fadd_rn(q, -zv);
        ob[(size_t)d * 1024 + j] = __fadd_rn(zv, diff);
        ls += diff * diff;
    }

    rs[t] = ls;
    __syncthreads();
    #pragma unroll
    for (int s = 128; s > 0; s >>= 1) {
        if (t < s) rs[t] += rs[t + s];
        __syncthreads();
    }
    if (t == 0) atomicAdd(&g_loss, rs[0]);
}

// k3: loss = 1.25 * mean((q - z)^2)
__global__ void fin_kernel(float* __restrict__ out) {
    out[Z_ELEMS + NROWS] = 1.25f * g_loss / (float)Z_ELEMS;
}

// ---------------------------------------------------------------------------
extern "C" void kernel_launch(void* const* d_in, const int* in_sizes, int n_in,
                              void* d_out, int out_size) {
    const float* z  = (const float*)d_in[0];
    const float* cb = (const float*)d_in[1];
    float* out = (float*)d_out;

    const int smem_bytes =
        (D * TM + 2 * TK * BS_STRIDE + 16 * TM) * 4   // Zs + Bs + Bsw + red_s
        + 16 * TM * 4                                  // red_i
        + TM * 4 * 3;                                  // best_s + best_i + zn_s

    cudaFuncSetAttribute(argmin_kernel,
                         cudaFuncAttributeMaxDynamicSharedMemorySize, smem_bytes);

    prep_kernel<<<4, 256>>>(cb);
    znorm_kernel<<<NROWS / 256, 256>>>(z);
    argmin_kernel<<<NROWS / TM, 256, smem_bytes>>>(z, cb, out + Z_ELEMS);
    gather_kernel<<<NROWS / 32, 256>>>(z, cb, out);
    fin_kernel<<<1, 1>>>(out);
}

// round 6
// speedup vs baseline: 1.9665x; 1.9665x over previous
#include <cuda_runtime.h>
#include <cuda_bf16.h>
#include <cstdint>

#define D       256
#define Kc      1024
#define NROWS   32768
#define Z_ELEMS 8388608
#define CAP     32
#define ASTRIDE 264          // bf16 row stride in smem (256 + 8 pad -> 528B rows)

typedef unsigned int u32;
typedef unsigned short u16;

// ---------------- device globals (no cudaMalloc allowed) -------------------
__device__ float g_cnorm[Kc];
__device__ float g_cnpart[4];
__device__ float g_znorm[NROWS];
__device__ int   g_idx[NROWS];
__device__ float g_loss;
__device__ uint4 g_Abf4[NROWS * 32];     // bf16(-2z), [n][256] row-major
__device__ uint4 g_cbbf4[Kc * 32];       // bf16(cb),  [k][256] row-major
__device__ u16   g_cand[NROWS * CAP];
__device__ unsigned char g_ccnt[NROWS];

// ---------------- helpers --------------------------------------------------
__device__ __forceinline__ u32 smem_u32(const void* p) {
    u32 a; asm("{ .reg .u64 t; cvta.to.shared.u64 t, %1; cvt.u32.u64 %0, t; }" : "=r"(a) : "l"(p));
    return a;
}
__device__ __forceinline__ void ldsm4(u32* r, u32 addr) {
    asm volatile("ldmatrix.sync.aligned.m8n8.x4.shared.b16 {%0,%1,%2,%3}, [%4];"
        : "=r"(r[0]), "=r"(r[1]), "=r"(r[2]), "=r"(r[3]) : "r"(addr));
}
__device__ __forceinline__ void mma16816(float* c, const u32* a, u32 b0, u32 b1) {
    asm volatile("mma.sync.aligned.m16n8k16.row.col.f32.bf16.bf16.f32 "
        "{%0,%1,%2,%3}, {%4,%5,%6,%7}, {%8,%9}, {%0,%1,%2,%3};"
        : "+f"(c[0]), "+f"(c[1]), "+f"(c[2]), "+f"(c[3])
        : "r"(a[0]), "r"(a[1]), "r"(a[2]), "r"(a[3]), "r"(b0), "r"(b1));
}
// monotonic float<->int for atomicMin (handles negatives too)
__device__ __forceinline__ int f2ord(float f) {
    int i = __float_as_int(f);
    return i >= 0 ? i : i ^ 0x7FFFFFFF;
}
__device__ __forceinline__ float ord2f(int i) {
    return __int_as_float(i >= 0 ? i : i ^ 0x7FFFFFFF);
}

// ---------------------------------------------------------------------------
// k0: exact code norms (sequential unfused fp32) + per-block max + loss reset
// ---------------------------------------------------------------------------
__global__ void prep_kernel(const float* __restrict__ cb) {
    __shared__ float red[256];
    int t = threadIdx.x;
    int k = blockIdx.x * 256 + t;
    if (k == 0) g_loss = 0.0f;
    const float* row = cb + (size_t)k * D;
    float s = 0.0f;
    for (int i = 0; i < D; ++i) {
        float v = row[i];
        s = __fadd_rn(s, __fmul_rn(v, v));
    }
    g_cnorm[k] = s;
    red[t] = s;
    __syncthreads();
    for (int st = 128; st > 0; st >>= 1) {
        if (t < st) red[t] = fmaxf(red[t], red[t + st]);
        __syncthreads();
    }
    if (t == 0) g_cnpart[blockIdx.x] = red[0];
}

// ---------------------------------------------------------------------------
// k1: fused exact z-norm + bf16(-2z) transpose to [n][256] row-major.
// ---------------------------------------------------------------------------
__global__ void __launch_bounds__(128)
zconv_kernel(const float* __restrict__ z) {
    extern __shared__ u16 sm16[];   // [128][264]
    const int t  = threadIdx.x;
    const int n0 = blockIdx.x * 128;
    const int b  = n0 >> 10;
    const int hw = (n0 & 1023) + t;
    const float* zb = z + (size_t)b * (D * 1024) + hw;

    float s = 0.0f;
    for (int d0 = 0; d0 < D; d0 += 8) {
        u16 pk[8];
        #pragma unroll
        for (int i = 0; i < 8; ++i) {
            float v = zb[(size_t)(d0 + i) * 1024];
            s = __fadd_rn(s, __fmul_rn(v, v));        // exact sequential ascending d
            __nv_bfloat16 h = __float2bfloat16(-2.0f * v);
            pk[i] = *(u16*)&h;
        }
        *(uint4*)&sm16[t * ASTRIDE + d0] = *(uint4*)pk;
    }
    g_znorm[n0 + t] = s;
    __syncthreads();
    const uint4* s4 = (const uint4*)sm16;
    for (int i = t; i < 128 * 32; i += 128) {
        int r = i >> 5, c = i & 31;
        g_Abf4[(size_t)(n0 + r) * 32 + c] = s4[(r * ASTRIDE * 2 + c * 16) >> 4];
    }
}

// k2: codebook -> bf16, elementwise (layout already [k][d] row-major)
__global__ void cbconv_kernel(const float* __restrict__ cb) {
    int i = blockIdx.x * 256 + threadIdx.x;
    __nv_bfloat16 h = __float2bfloat16(cb[i]);
    ((u16*)g_cbbf4)[i] = *(u16*)&h;
}

// ---------------------------------------------------------------------------
// k3: mma.sync bf16 GEMM (128 rows x 1024 codes, K=256) + candidate filter.
// 8 warps: warp_m = wid&3 (32 rows), warp_n = wid>>2 (64 codes).
// Filter: per-row running min (atomicMin on ordered-int) then push codes with
// g <= rowmin + margin. margin = 2^-6*sqrt(zn*cnmax) + 3e-4 covers the 2x
// bf16 product error bound + reference fp32 quantization -> true argmin
// (and all its quantized ties) guaranteed collected.
// ---------------------------------------------------------------------------
__global__ void __launch_bounds__(256, 1)
mma_cand_kernel(void) {
    extern __shared__ char smr[];
    u16*   Asm    = (u16*)smr;                         // [128][264]
    u16*   Bsm    = (u16*)(smr + 67584);               // [128][264]
    float* cn_s   = (float*)(smr + 135168);            // [1024]
    float* marg_s = cn_s + 1024;                       // [128]
    int*   rmin_s = (int*)(marg_s + 128);              // [128]
    int*   cnt_s  = rmin_s + 128;                      // [128]
    u16*   cand_s = (u16*)(cnt_s + 128);               // [128][CAP]

    const int t      = threadIdx.x;
    const int lane   = t & 31;
    const int wid    = t >> 5;
    const int warp_m = wid & 3;
    const int warp_n = wid >> 2;
    const int gid    = lane >> 2;
    const int tig    = lane & 3;
    const int n0     = blockIdx.x * 128;

    {   // A tile load (padded), cn, margins, init
        uint4* A4 = (uint4*)Asm;
        const uint4* gA = g_Abf4 + (size_t)n0 * 32;
        for (int i = t; i < 128 * 32; i += 256) {
            int r = i >> 5, c = i & 31;
            A4[(r * ASTRIDE * 2 + c * 16) >> 4] = gA[i];
        }
        for (int i = t; i < Kc; i += 256) cn_s[i] = g_cnorm[i];
        if (t < 128) {
            float zn = g_znorm[n0 + t];
            float cm = fmaxf(fmaxf(g_cnpart[0], g_cnpart[1]),
                             fmaxf(g_cnpart[2], g_cnpart[3]));
            marg_s[t] = 0.015625f * sqrtf(zn * cm) + 3e-4f;
            rmin_s[t] = 0x7F800000;   // +inf
            cnt_s[t]  = 0;
        }
    }
    __syncthreads();

    const u32 Abase = smem_u32(Asm);
    const u32 Bbase = smem_u32(Bsm);

    for (int nt = 0; nt < 8; ++nt) {
        {   // B tile load
            uint4* B4 = (uint4*)Bsm;
            const uint4* gB = g_cbbf4 + (size_t)nt * 128 * 32;
            for (int i = t; i < 128 * 32; i += 256) {
                int r = i >> 5, c = i & 31;
                B4[(r * ASTRIDE * 2 + c * 16) >> 4] = gB[i];
            }
        }
        __syncthreads();

        float acc[2][8][4];
        #pragma unroll
        for (int mt = 0; mt < 2; ++mt)
            #pragma unroll
            for (int j = 0; j < 8; ++j)
                #pragma unroll
                for (int c = 0; c < 4; ++c) acc[mt][j][c] = 0.0f;

        for (int kc = 0; kc < D; kc += 16) {
            u32 a[2][4], bq[4][4];
            #pragma unroll
            for (int mt = 0; mt < 2; ++mt) {
                int r  = warp_m * 32 + mt * 16 + (lane & 15);
                int ko = kc + ((lane >> 4) << 3);
                ldsm4(a[mt], Abase + (u32)((r * ASTRIDE + ko) * 2));
            }
            #pragma unroll
            for (int p = 0; p < 4; ++p) {
                int code = warp_n * 64 + p * 16 + ((lane >> 4) & 1) * 8 + (lane & 7);
                int ko   = kc + ((lane >> 3) & 1) * 8;
                ldsm4(bq[p], Bbase + (u32)((code * ASTRIDE + ko) * 2));
            }
            #pragma unroll
            for (int mt = 0; mt < 2; ++mt)
                #pragma unroll
                for (int p = 0; p < 4; ++p) {
                    mma16816(acc[mt][2 * p    ], a[mt], bq[p][0], bq[p][1]);
                    mma16816(acc[mt][2 * p + 1], a[mt], bq[p][2], bq[p][3]);
                }
        }

        // ---- epilogue: per-row min then candidate push ----
        float cnv[16];
        #pragma unroll
        for (int j = 0; j < 8; ++j) {
            int cd = nt * 128 + warp_n * 64 + j * 8 + tig * 2;
            cnv[j * 2]     = cn_s[cd];
            cnv[j * 2 + 1] = cn_s[cd + 1];
        }
        float rm[4] = {3.4e38f, 3.4e38f, 3.4e38f, 3.4e38f}; // mt0:{gid,gid+8}, mt1:{...}
        #pragma unroll
        for (int mt = 0; mt < 2; ++mt)
            #pragma unroll
            for (int j = 0; j < 8; ++j)
                #pragma unroll
                for (int c = 0; c < 2; ++c) {
                    float g0 = cnv[j * 2 + c] + acc[mt][j][c];       // row gid
                    float g1 = cnv[j * 2 + c] + acc[mt][j][2 + c];   // row gid+8
                    rm[mt * 2]     = fminf(rm[mt * 2], g0);
                    rm[mt * 2 + 1] = fminf(rm[mt * 2 + 1], g1);
                }
        #pragma unroll
        for (int r4 = 0; r4 < 4; ++r4) {
            rm[r4] = fminf(rm[r4], __shfl_xor_sync(0xFFFFFFFF, rm[r4], 1));
            rm[r4] = fminf(rm[r4], __shfl_xor_sync(0xFFFFFFFF, rm[r4], 2));
        }
        if (tig == 0) {
            #pragma unroll
            for (int r4 = 0; r4 < 4; ++r4) {
                int row = warp_m * 32 + (r4 >> 1) * 16 + (r4 & 1) * 8 + gid;
                atomicMin(&rmin_s[row], f2ord(rm[r4]));
            }
        }
        __syncthreads();

        float thr[4];
        #pragma unroll
        for (int r4 = 0; r4 < 4; ++r4) {
            int row = warp_m * 32 + (r4 >> 1) * 16 + (r4 & 1) * 8 + gid;
            thr[r4] = ord2f(rmin_s[row]) + marg_s[row];
        }
        #pragma unroll
        for (int mt = 0; mt < 2; ++mt)
            #pragma unroll
            for (int j = 0; j < 8; ++j)
                #pragma unroll
                for (int c = 0; c < 2; ++c) {
                    int code = nt * 128 + warp_n * 64 + j * 8 + tig * 2 + c;
                    float g0 = cnv[j * 2 + c] + acc[mt][j][c];
                    float g1 = cnv[j * 2 + c] + acc[mt][j][2 + c];
                    if (g0 <= thr[mt * 2]) {
                        int row = warp_m * 32 + mt * 16 + gid;
                        int sl = atomicAdd(&cnt_s[row], 1);
                        if (sl < CAP) cand_s[row * CAP + sl] = (u16)code;
                    }
                    if (g1 <= thr[mt * 2 + 1]) {
                        int row = warp_m * 32 + mt * 16 + 8 + gid;
                        int sl = atomicAdd(&cnt_s[row], 1);
                        if (sl < CAP) cand_s[row * CAP + sl] = (u16)code;
                    }
                }
        __syncthreads();
    }

    if (t < 128) {
        int c = cnt_s[t];
        g_ccnt[n0 + t] = (c > CAP) ? 255 : (unsigned char)c;
    }
    for (int i = t; i < 128 * CAP; i += 256)
        g_cand[(size_t)n0 * CAP + i] = cand_s[i];
}

// ---------------------------------------------------------------------------
// k4: exact verification. Bit-exact reference score (sequential ascending-d
// fmaf; fl(fl(zn+cn)-fl(2*dot))); lexicographic (score, code) min reproduces
// jnp.argmin first-occurrence regardless of candidate order.
// ---------------------------------------------------------------------------
__global__ void __launch_bounds__(256)
exact_kernel(const float* __restrict__ z, const float* __restrict__ cb,
             float* __restrict__ out_idx_f) {
    int n  = blockIdx.x * 256 + threadIdx.x;
    int b  = n >> 10;
    int hw = n & 1023;
    const float* zb = z + (size_t)b * (D * 1024) + hw;
    float zn  = g_znorm[n];
    int   cnt = g_ccnt[n];

    float best = 3.4e38f;
    int   bi   = Kc;
    if (cnt <= CAP) {
        for (int i = 0; i < cnt; ++i) {
            int code = g_cand[(size_t)n * CAP + i] & 1023;
            const float* cr = cb + (size_t)code * D;
            float dot = 0.0f;
            #pragma unroll 8
            for (int d = 0; d < D; ++d)
                dot = fmaf(zb[(size_t)d * 1024], cr[d], dot);
            float t1 = __fadd_rn(zn, g_cnorm[code]);
            float sc = __fadd_rn(t1, __fmul_rn(-2.0f, dot));
            if (sc < best || (sc == best && code < bi)) { best = sc; bi = code; }
        }
    } else {   // overflow fallback: exact full scan (ascending, strict <)
        for (int code = 0; code < Kc; ++code) {
            const float* cr = cb + (size_t)code * D;
            float dot = 0.0f;
            for (int d = 0; d < D; ++d)
                dot = fmaf(zb[(size_t)d * 1024], cr[d], dot);
            float t1 = __fadd_rn(zn, g_cnorm[code]);
            float sc = __fadd_rn(t1, __fmul_rn(-2.0f, dot));
            if (sc < best) { best = sc; bi = code; }
        }
    }
    if (bi >= Kc) bi = 0;
    g_idx[n] = bi;
    out_idx_f[n] = (float)bi;
}

// ---------------------------------------------------------------------------
// k5: tiled gather + STE + loss (validated R3: coalesced, ~29us)
// ---------------------------------------------------------------------------
__global__ void __launch_bounds__(256)
gather_kernel(const float* __restrict__ z, const float* __restrict__ cb,
              float* __restrict__ out) {
    __shared__ float q_s[32][257];
    __shared__ int   ci_s[32];
    __shared__ float rs[256];

    const int t   = threadIdx.x;
    const int n0  = blockIdx.x * 32;
    const int b   = n0 >> 10;
    const int hw0 = n0 & 1023;

    if (t < 32) ci_s[t] = g_idx[n0 + t];
    __syncthreads();
    for (int i = t; i < 32 * 256; i += 256) {
        int j = i >> 8, d = i & 255;
        q_s[j][d] = cb[(size_t)ci_s[j] * D + d];
    }
    __syncthreads();

    const float* zb = z   + (size_t)b * (D * 1024) + hw0;
    float*       ob = out + (size_t)b * (D * 1024) + hw0;
    float ls = 0.0f;
    #pragma unroll 4
    for (int i = t; i < 32 * 256; i += 256) {
        int d = i >> 5, j = i & 31;
        float zv   = zb[(size_t)d * 1024 + j];
        float q    = q_s[j][d];
        float diff = __fadd_rn(q, -zv);
        ob[(size_t)d * 1024 + j] = __fadd_rn(zv, diff);
        ls += diff * diff;
    }
    rs[t] = ls;
    __syncthreads();
    #pragma unroll
    for (int s = 128; s > 0; s >>= 1) {
        if (t < s) rs[t] += rs[t + s];
        __syncthreads();
    }
    if (t == 0) atomicAdd(&g_loss, rs[0]);
}

__global__ void fin_kernel(float* __restrict__ out) {
    out[Z_ELEMS + NROWS] = 1.25f * g_loss / (float)Z_ELEMS;
}

// ---------------------------------------------------------------------------
extern "C" void kernel_launch(void* const* d_in, const int* in_sizes, int n_in,
                              void* d_out, int out_size) {
    const float* z  = (const float*)d_in[0];
    const float* cb = (const float*)d_in[1];
    float* out = (float*)d_out;

    const int zconv_smem = 128 * ASTRIDE * 2;                 // 67584
    const int mma_smem   = 67584 * 2 + 4096 + 128 * 4 * 3 + 128 * CAP * 2;

    cudaFuncSetAttribute(zconv_kernel,
                         cudaFuncAttributeMaxDynamicSharedMemorySize, zconv_smem);
    cudaFuncSetAttribute(mma_cand_kernel,
                         cudaFuncAttributeMaxDynamicSharedMemorySize, mma_smem);

    prep_kernel<<<4, 256>>>(cb);
    zconv_kernel<<<NROWS / 128, 128, zconv_smem>>>(z);
    cbconv_kernel<<<Kc * D / 256, 256>>>(cb);
    mma_cand_kernel<<<NROWS / 128, 256, mma_smem>>>();
    exact_kernel<<<NROWS / 256, 256>>>(z, cb, out + Z_ELEMS);
    gather_kernel<<<NROWS / 32, 256>>>(z, cb, out);
    fin_kernel<<<1, 1>>>(out);
}

// round 7
// speedup vs baseline: 2.0269x; 1.0307x over previous
#include <cuda_runtime.h>
#include <cuda_bf16.h>
#include <cstdint>

#define D       256
#define Kc      1024
#define NROWS   32768
#define Z_ELEMS 8388608
#define CAP     32
#define ASTRIDE 264          // bf16 row stride in smem (256 + 8 pad -> 528B rows)
#define TILE_B  67584        // 128 rows * 528 B

typedef unsigned int u32;
typedef unsigned short u16;

// ---------------- device globals (no cudaMalloc allowed) -------------------
__device__ float g_cnorm[Kc];
__device__ float g_cnpart[4];
__device__ float g_znorm[NROWS];
__device__ int   g_idx[NROWS];
__device__ float g_loss;
__device__ uint4 g_cbbf4[Kc * 32];       // bf16(cb), [k][256] row-major (512B/row)
__device__ u16   g_cand[NROWS * CAP];
__device__ unsigned char g_ccnt[NROWS];

// ---------------- helpers --------------------------------------------------
__device__ __forceinline__ u32 smem_u32(const void* p) {
    u32 a; asm("{ .reg .u64 t; cvta.to.shared.u64 t, %1; cvt.u32.u64 %0, t; }" : "=r"(a) : "l"(p));
    return a;
}
__device__ __forceinline__ void ldsm4(u32* r, u32 addr) {
    asm volatile("ldmatrix.sync.aligned.m8n8.x4.shared.b16 {%0,%1,%2,%3}, [%4];"
        : "=r"(r[0]), "=r"(r[1]), "=r"(r[2]), "=r"(r[3]) : "r"(addr));
}
__device__ __forceinline__ void mma16816(float* c, const u32* a, u32 b0, u32 b1) {
    asm volatile("mma.sync.aligned.m16n8k16.row.col.f32.bf16.bf16.f32 "
        "{%0,%1,%2,%3}, {%4,%5,%6,%7}, {%8,%9}, {%0,%1,%2,%3};"
        : "+f"(c[0]), "+f"(c[1]), "+f"(c[2]), "+f"(c[3])
        : "r"(a[0]), "r"(a[1]), "r"(a[2]), "r"(a[3]), "r"(b0), "r"(b1));
}
__device__ __forceinline__ void cpasync16(u32 dst, const void* src) {
    asm volatile("cp.async.cg.shared.global [%0], [%1], 16;" :: "r"(dst), "l"(src));
}
__device__ __forceinline__ void cpcommit() {
    asm volatile("cp.async.commit_group;" ::: "memory");
}
__device__ __forceinline__ void cpwait0() {
    asm volatile("cp.async.wait_group 0;" ::: "memory");
}
__device__ __forceinline__ int f2ord(float f) {
    int i = __float_as_int(f);
    return i >= 0 ? i : i ^ 0x7FFFFFFF;
}
__device__ __forceinline__ float ord2f(int i) {
    return __int_as_float(i >= 0 ? i : i ^ 0x7FFFFFFF);
}

// ---------------------------------------------------------------------------
// k0: coalesced smem-staged codebook pass: exact sequential cnorm (bit-exact),
// bf16 convert, per-block max, loss reset. grid 4 x 256.
// ---------------------------------------------------------------------------
__global__ void __launch_bounds__(256)
prep_kernel(const float* __restrict__ cb) {
    __shared__ float stage[256 * 33];
    __shared__ float red[256];
    const int t  = threadIdx.x;
    const int c0 = blockIdx.x * 256;
    if (blockIdx.x == 0 && t == 0) g_loss = 0.0f;

    float s = 0.0f;
    for (int ch = 0; ch < 8; ++ch) {
        __syncthreads();
        for (int i = t; i < 256 * 32; i += 256) {
            int c = i >> 5, d = i & 31;
            float v = cb[(size_t)(c0 + c) * D + ch * 32 + d];
            stage[c * 33 + d] = v;
            __nv_bfloat16 h = __float2bfloat16(v);
            ((u16*)g_cbbf4)[(size_t)(c0 + c) * D + ch * 32 + d] = *(u16*)&h;
        }
        __syncthreads();
        #pragma unroll
        for (int d = 0; d < 32; ++d) {
            float v = stage[t * 33 + d];
            s = __fadd_rn(s, __fmul_rn(v, v));   // sequential ascending d, unfused
        }
    }
    g_cnorm[c0 + t] = s;
    red[t] = s;
    __syncthreads();
    for (int st = 128; st > 0; st >>= 1) {
        if (t < st) red[t] = fmaxf(red[t], red[t + st]);
        __syncthreads();
    }
    if (t == 0) g_cnpart[blockIdx.x] = red[0];
}

// ---------------------------------------------------------------------------
// k1: fused (z->bf16 A tile + exact znorm) prologue, cp.async double-buffered
// B mainloop, mma.sync bf16 GEMM 128 rows x 1024 codes, barrier-free filter.
// Threshold = min(warp running row-min, smem rmin) + margin: monotone
// conservative -> collected set is always a superset of exact argmin + ties.
// ---------------------------------------------------------------------------
__global__ void __launch_bounds__(256, 1)
mma_cand_kernel(const float* __restrict__ z) {
    extern __shared__ char smr[];
    u16*   Asm    = (u16*)smr;                         // [128][264]
    // B stages at smr + TILE_B, smr + 2*TILE_B
    float* cn_s   = (float*)(smr + 3 * TILE_B);        // [1024]
    float* marg_s = cn_s + 1024;                       // [128]
    int*   rmin_s = (int*)(marg_s + 128);              // [128]
    int*   cnt_s  = rmin_s + 128;                      // [128]
    u16*   cand_s = (u16*)(cnt_s + 128);               // [128][CAP]

    const int t      = threadIdx.x;
    const int lane   = t & 31;
    const int wid    = t >> 5;
    const int warp_m = wid & 3;
    const int warp_n = wid >> 2;
    const int gid    = lane >> 2;
    const int tig    = lane & 3;
    const int n0     = blockIdx.x * 128;

    const u32 Abase = smem_u32(Asm);
    const u32 Bbase = Abase + TILE_B;

    // ---- prefetch B tile 0 ----
    {
        const char* src = ((const char*)g_cbbf4);
        for (int i = t; i < 4096; i += 256) {
            int r = i >> 5, c = i & 31;
            cpasync16(Bbase + (u32)(r * 528 + c * 16), src + r * 512 + c * 16);
        }
        cpcommit();
    }

    // ---- prologue: A conversion + exact znorm (threads<128); cn (others) ----
    if (t < 128) {
        const int b  = n0 >> 10;
        const int hw = (n0 & 1023) + t;
        const float* zb = z + (size_t)b * (D * 1024) + hw;
        float s = 0.0f;
        for (int d0 = 0; d0 < D; d0 += 8) {
            u16 pk[8];
            #pragma unroll
            for (int i = 0; i < 8; ++i) {
                float v = zb[(size_t)(d0 + i) * 1024];
                s = __fadd_rn(s, __fmul_rn(v, v));      // exact sequential ascending d
                __nv_bfloat16 h = __float2bfloat16(-2.0f * v);
                pk[i] = *(u16*)&h;
            }
            *(uint4*)&Asm[t * ASTRIDE + d0] = *(uint4*)pk;
        }
        g_znorm[n0 + t] = s;
        float cm = fmaxf(fmaxf(g_cnpart[0], g_cnpart[1]),
                         fmaxf(g_cnpart[2], g_cnpart[3]));
        marg_s[t] = 0.015625f * sqrtf(s * cm) + 3e-4f;
        rmin_s[t] = 0x7F800000;
        cnt_s[t]  = 0;
    } else {
        for (int i = t - 128; i < Kc; i += 128) cn_s[i] = g_cnorm[i];
    }

    float rm[4] = {3.4e38f, 3.4e38f, 3.4e38f, 3.4e38f};  // running per-warp row minima
    int   rowv[4];
    #pragma unroll
    for (int r4 = 0; r4 < 4; ++r4)
        rowv[r4] = warp_m * 32 + (r4 >> 1) * 16 + (r4 & 1) * 8 + gid;

    for (int nt = 0; nt < 8; ++nt) {
        cpwait0();
        __syncthreads();   // B[nt] visible; prior compute/epilogue done everywhere
        if (nt < 7) {      // prefetch B[nt+1] into the other stage (safe post-sync)
            const char* src = ((const char*)g_cbbf4) + (size_t)(nt + 1) * 128 * 512;
            u32 dstb = Bbase + (u32)(((nt + 1) & 1) * TILE_B);
            for (int i = t; i < 4096; i += 256) {
                int r = i >> 5, c = i & 31;
                cpasync16(dstb + (u32)(r * 528 + c * 16), src + r * 512 + c * 16);
            }
            cpcommit();
        }
        const u32 Bb = Bbase + (u32)((nt & 1) * TILE_B);

        float acc[2][8][4];
        #pragma unroll
        for (int mt = 0; mt < 2; ++mt)
            #pragma unroll
            for (int j = 0; j < 8; ++j)
                #pragma unroll
                for (int c = 0; c < 4; ++c) acc[mt][j][c] = 0.0f;

        #pragma unroll 4
        for (int kc = 0; kc < D; kc += 16) {
            u32 a[2][4], bq[4][4];
            #pragma unroll
            for (int mt = 0; mt < 2; ++mt) {
                int r  = warp_m * 32 + mt * 16 + (lane & 15);
                int ko = kc + ((lane >> 4) << 3);
                ldsm4(a[mt], Abase + (u32)((r * ASTRIDE + ko) * 2));
            }
            #pragma unroll
            for (int p = 0; p < 4; ++p) {
                int code = warp_n * 64 + p * 16 + ((lane >> 4) & 1) * 8 + (lane & 7);
                int ko   = kc + ((lane >> 3) & 1) * 8;
                ldsm4(bq[p], Bb + (u32)((code * ASTRIDE + ko) * 2));
            }
            #pragma unroll
            for (int mt = 0; mt < 2; ++mt)
                #pragma unroll
                for (int p = 0; p < 4; ++p) {
                    mma16816(acc[mt][2 * p    ], a[mt], bq[p][0], bq[p][1]);
                    mma16816(acc[mt][2 * p + 1], a[mt], bq[p][2], bq[p][3]);
                }
        }

        // ---- barrier-free epilogue ----
        float cnv[16];
        #pragma unroll
        for (int j = 0; j < 8; ++j) {
            int cd = nt * 128 + warp_n * 64 + j * 8 + tig * 2;
            cnv[j * 2]     = cn_s[cd];
            cnv[j * 2 + 1] = cn_s[cd + 1];
        }
        #pragma unroll
        for (int mt = 0; mt < 2; ++mt)
            #pragma unroll
            for (int j = 0; j < 8; ++j)
                #pragma unroll
                for (int c = 0; c < 2; ++c) {
                    float g0 = cnv[j * 2 + c] + acc[mt][j][c];       // row gid
                    float g1 = cnv[j * 2 + c] + acc[mt][j][2 + c];   // row gid+8
                    rm[mt * 2]     = fminf(rm[mt * 2], g0);
                    rm[mt * 2 + 1] = fminf(rm[mt * 2 + 1], g1);
                }
        #pragma unroll
        for (int r4 = 0; r4 < 4; ++r4) {
            rm[r4] = fminf(rm[r4], __shfl_xor_sync(0xFFFFFFFF, rm[r4], 1));
            rm[r4] = fminf(rm[r4], __shfl_xor_sync(0xFFFFFFFF, rm[r4], 2));
        }
        if (tig == 0) {
            #pragma unroll
            for (int r4 = 0; r4 < 4; ++r4)
                atomicMin(&rmin_s[rowv[r4]], f2ord(rm[r4]));
        }
        float thr[4];
        #pragma unroll
        for (int r4 = 0; r4 < 4; ++r4)
            thr[r4] = fminf(rm[r4], ord2f(rmin_s[rowv[r4]])) + marg_s[rowv[r4]];

        #pragma unroll
        for (int mt = 0; mt < 2; ++mt)
            #pragma unroll
            for (int j = 0; j < 8; ++j)
                #pragma unroll
                for (int c = 0; c < 2; ++c) {
                    int code = nt * 128 + warp_n * 64 + j * 8 + tig * 2 + c;
                    float g0 = cnv[j * 2 + c] + acc[mt][j][c];
                    float g1 = cnv[j * 2 + c] + acc[mt][j][2 + c];
                    if (g0 <= thr[mt * 2]) {
                        int row = warp_m * 32 + mt * 16 + gid;
                        int sl = atomicAdd(&cnt_s[row], 1);
                        if (sl < CAP) cand_s[row * CAP + sl] = (u16)code;
                    }
                    if (g1 <= thr[mt * 2 + 1]) {
                        int row = warp_m * 32 + mt * 16 + 8 + gid;
                        int sl = atomicAdd(&cnt_s[row], 1);
                        if (sl < CAP) cand_s[row * CAP + sl] = (u16)code;
                    }
                }
    }
    __syncthreads();

    if (t < 128) {
        int c = cnt_s[t];
        g_ccnt[n0 + t] = (c > CAP) ? 255 : (unsigned char)c;
    }
    for (int i = t; i < 128 * CAP; i += 256)
        g_cand[(size_t)n0 * CAP + i] = cand_s[i];
}

// ---------------------------------------------------------------------------
// k2: exact verification. cnt==1 shortcut; else bit-exact reference score
// (sequential ascending-d fmaf; fl(fl(zn+cn)-fl(2*dot))) with lexicographic
// (score, code) min == jnp.argmin first occurrence.
// ---------------------------------------------------------------------------
__global__ void __launch_bounds__(256)
exact_kernel(const float* __restrict__ z, const float* __restrict__ cb,
             float* __restrict__ out_idx_f) {
    int n  = blockIdx.x * 256 + threadIdx.x;
    int b  = n >> 10;
    int hw = n & 1023;
    const float* zb = z + (size_t)b * (D * 1024) + hw;
    int cnt = g_ccnt[n];

    int bi;
    if (cnt == 1) {
        bi = g_cand[(size_t)n * CAP] & 1023;
    } else if (cnt <= CAP) {
        float zn = g_znorm[n];
        float best = 3.4e38f;
        bi = Kc;
        for (int i = 0; i < cnt; ++i) {
            int code = g_cand[(size_t)n * CAP + i] & 1023;
            const float* cr = cb + (size_t)code * D;
            float dot = 0.0f;
            #pragma unroll 8
            for (int d = 0; d < D; ++d)
                dot = fmaf(zb[(size_t)d * 1024], cr[d], dot);
            float t1 = __fadd_rn(zn, g_cnorm[code]);
            float sc = __fadd_rn(t1, __fmul_rn(-2.0f, dot));
            if (sc < best || (sc == best && code < bi)) { best = sc; bi = code; }
        }
        if (bi >= Kc) bi = 0;
    } else {   // overflow fallback: exact full scan (ascending, strict <)
        float zn = g_znorm[n];
        float best = 3.4e38f;
        bi = 0;
        for (int code = 0; code < Kc; ++code) {
            const float* cr = cb + (size_t)code * D;
            float dot = 0.0f;
            #pragma unroll 8
            for (int d = 0; d < D; ++d)
                dot = fmaf(zb[(size_t)d * 1024], cr[d], dot);
            float t1 = __fadd_rn(zn, g_cnorm[code]);
            float sc = __fadd_rn(t1, __fmul_rn(-2.0f, dot));
            if (sc < best) { best = sc; bi = code; }
        }
    }
    g_idx[n] = bi;
    out_idx_f[n] = (float)bi;
}

// ---------------------------------------------------------------------------
// k3: tiled gather + STE + loss (validated: coalesced, ~29us)
// ---------------------------------------------------------------------------
__global__ void __launch_bounds__(256)
gather_kernel(const float* __restrict__ z, const float* __restrict__ cb,
              float* __restrict__ out) {
    __shared__ float q_s[32][257];
    __shared__ int   ci_s[32];
    __shared__ float rs[256];

    const int t   = threadIdx.x;
    const int n0  = blockIdx.x * 32;
    const int b   = n0 >> 10;
    const int hw0 = n0 & 1023;

    if (t < 32) ci_s[t] = g_idx[n0 + t];
    __syncthreads();
    for (int i = t; i < 32 * 256; i += 256) {
        int j = i >> 8, d = i & 255;
        q_s[j][d] = cb[(size_t)ci_s[j] * D + d];
    }
    __syncthreads();

    const float* zb = z   + (size_t)b * (D * 1024) + hw0;
    float*       ob = out + (size_t)b * (D * 1024) + hw0;
    float ls = 0.0f;
    #pragma unroll 4
    for (int i = t; i < 32 * 256; i += 256) {
        int d = i >> 5, j = i & 31;
        float zv   = zb[(size_t)d * 1024 + j];
        float q    = q_s[j][d];
        float diff = __fadd_rn(q, -zv);
        ob[(size_t)d * 1024 + j] = __fadd_rn(zv, diff);
        ls += diff * diff;
    }
    rs[t] = ls;
    __syncthreads();
    #pragma unroll
    for (int s = 128; s > 0; s >>= 1) {
        if (t < s) rs[t] += rs[t + s];
        __syncthreads();
    }
    if (t == 0) atomicAdd(&g_loss, rs[0]);
}

__global__ void fin_kernel(float* __restrict__ out) {
    out[Z_ELEMS + NROWS] = 1.25f * g_loss / (float)Z_ELEMS;
}

// ---------------------------------------------------------------------------
extern "C" void kernel_launch(void* const* d_in, const int* in_sizes, int n_in,
                              void* d_out, int out_size) {
    const float* z  = (const float*)d_in[0];
    const float* cb = (const float*)d_in[1];
    float* out = (float*)d_out;

    const int mma_smem = 3 * TILE_B + 4096 + 128 * 4 * 3 + 128 * CAP * 2; // 216576

    cudaFuncSetAttribute(mma_cand_kernel,
                         cudaFuncAttributeMaxDynamicSharedMemorySize, mma_smem);

    prep_kernel<<<4, 256>>>(cb);
    mma_cand_kernel<<<NROWS / 128, 256, mma_smem>>>(z);
    exact_kernel<<<NROWS / 256, 256>>>(z, cb, out + Z_ELEMS);
    gather_kernel<<<NROWS / 32, 256>>>(z, cb, out);
    fin_kernel<<<1, 1>>>(out);
}